// round 4
// baseline (speedup 1.0000x reference)
#include <cuda_runtime.h>

// Problem constants (fixed by the reference)
#define NXC 432
#define NYC 496
#define GC  (NXC * NYC)   // 214272 cells per batch image
#define BC  4
#define CC  64

// cell -> pillar index map, -1 = empty. Static device scratch (no allocs allowed).
__device__ int g_map[BC * GC];

// ---------------------------------------------------------------------------
// Kernel 1: init map to -1 (vectorized int4)
// ---------------------------------------------------------------------------
__global__ void init_map_kernel() {
    int i = blockIdx.x * blockDim.x + threadIdx.x;
    int4* m4 = reinterpret_cast<int4*>(g_map);
    if (i < (BC * GC) / 4) {
        m4[i] = make_int4(-1, -1, -1, -1);
    }
}

// ---------------------------------------------------------------------------
// Kernel 2: scatter pillar ids into the map
// coords row: (b, z, y, x); gidx = b*G + z + y*NX + x  (z == 0)
// Cells are unique per batch -> no write conflicts.
// ---------------------------------------------------------------------------
__global__ void fill_map_kernel(const int* __restrict__ vc, int P) {
    int p = blockIdx.x * blockDim.x + threadIdx.x;
    if (p < P) {
        int4 c = reinterpret_cast<const int4*>(vc)[p];  // (b, z, y, x)
        int mi = c.x * GC + c.y + c.z * NXC + c.w;
        g_map[mi] = p;
    }
}

// ---------------------------------------------------------------------------
// Kernel 3: gather-style output writer.
//   grid.y in [0, C/16): 16-channel group
//   grid.x * block covers spatial quads: q in [0, B*G/4)
// Each thread: reads map int4 for 4 consecutive cells, then for 4 sub-groups
// of 4 channels gathers pillar rows (float4 = 16B, contiguous 64B per lane
// per thread -> no sector waste) and writes 16 coalesced float4 stores.
// Output layout: out[((b*C + c)*G + s)]  (B, C, NY, NX).
// ---------------------------------------------------------------------------
__global__ void __launch_bounds__(256)
gather_out_kernel(const float4* __restrict__ pf4, float4* __restrict__ out4) {
    const int NQ_PER_B = GC / 4;           // 53568 quads per batch image
    int q = blockIdx.x * blockDim.x + threadIdx.x;   // global quad id, [0, B*G/4)
    // (grid sized exactly: B*G/4 = 214272 divisible by 256)

    int b  = q / NQ_PER_B;
    int s4 = q - b * NQ_PER_B;             // quad index within the image (float4 units)

    // map, viewed as int4: index == q (since q = b*NQ_PER_B + s4)
    int4 pv = reinterpret_cast<const int4*>(g_map)[q];

    int c0 = blockIdx.y * 16;              // first channel of this thread's group
    // output base (float4 units) for channel c0, this quad
    int base = (b * CC + c0) * NQ_PER_B + s4;

    const float4 z4 = make_float4(0.f, 0.f, 0.f, 0.f);

    int mx = max(max(pv.x, pv.y), max(pv.z, pv.w));
    if (mx < 0) {
        // fully empty quad: pure streaming zero-fill
        #pragma unroll
        for (int k = 0; k < 16; k++) {
            __stcs(&out4[base + k * NQ_PER_B], z4);
        }
        return;
    }

    #pragma unroll
    for (int cc = 0; cc < 4; cc++) {
        int cvec = (c0 >> 2) + cc;  // float4 column within the 16-float4 pillar row
        float4 r0 = (pv.x >= 0) ? __ldg(&pf4[pv.x * (CC / 4) + cvec]) : z4;
        float4 r1 = (pv.y >= 0) ? __ldg(&pf4[pv.y * (CC / 4) + cvec]) : z4;
        float4 r2 = (pv.z >= 0) ? __ldg(&pf4[pv.z * (CC / 4) + cvec]) : z4;
        float4 r3 = (pv.w >= 0) ? __ldg(&pf4[pv.w * (CC / 4) + cvec]) : z4;

        int ob = base + (cc * 4) * NQ_PER_B;
        __stcs(&out4[ob + 0 * NQ_PER_B], make_float4(r0.x, r1.x, r2.x, r3.x));
        __stcs(&out4[ob + 1 * NQ_PER_B], make_float4(r0.y, r1.y, r2.y, r3.y));
        __stcs(&out4[ob + 2 * NQ_PER_B], make_float4(r0.z, r1.z, r2.z, r3.z));
        __stcs(&out4[ob + 3 * NQ_PER_B], make_float4(r0.w, r1.w, r2.w, r3.w));
    }
}

// ---------------------------------------------------------------------------
// Inputs (metadata order):
//   0: pillar_features [P, 64] f32
//   1..6: W_off, b_off, W_step, b_step, W_prob, b_prob  (DEAD CODE: prob_buf
//         in the reference is never written, so p==0 and out == spatial)
//   7: voxel_coords [P, 4] i32
// Output: [B, C, NY, NX] f32
// ---------------------------------------------------------------------------
extern "C" void kernel_launch(void* const* d_in, const int* in_sizes, int n_in,
                              void* d_out, int out_size) {
    const float* pf = (const float*)d_in[0];
    const int*   vc = (const int*)d_in[7];
    int P = in_sizes[7] / 4;

    // 1) map = -1
    {
        int n = (BC * GC) / 4;            // 214272 int4s
        init_map_kernel<<<(n + 255) / 256, 256>>>();
    }
    // 2) scatter pillar ids
    fill_map_kernel<<<(P + 255) / 256, 256>>>(vc, P);

    // 3) gather + write full output (also handles the zero background)
    {
        int nq = (BC * GC) / 4;           // 214272 quads, exactly 837 blocks of 256
        dim3 grid(nq / 256, CC / 16);
        gather_out_kernel<<<grid, 256>>>((const float4*)pf, (float4*)d_out);
    }
}